// round 1
// baseline (speedup 1.0000x reference)
#include <cuda_runtime.h>
#include <cuda_bf16.h>

// FM layer: out[b, :] = 0.5 * ( (sum_i v_i*e_i)^2 - sum_i (v_i*e_i)^2 )
// over nnz i with batch_ids[i] == b (batch_ids sorted ascending).
//
// Inputs (metadata order):
//   d_in[0] feature_embedding  float32 [VOCAB=1e6, 64]
//   d_in[1] feature_vals       float32 [NNZ=819200]
//   d_in[2] batch_ids          int32   [NNZ] (sorted)
//   d_in[3] feat_ids           int32   [NNZ]
//   d_in[4] batch_size         int32   [1]   (4096)
// Output: float32 [4096, 64]

#define EMBED 64
#define GROUPS 4          // independent 64-thread groups per CTA
#define BLOCK (EMBED * GROUPS)

__global__ __launch_bounds__(BLOCK, 8)
void fm_kernel(const float* __restrict__ emb,
               const float* __restrict__ vals,
               const int*   __restrict__ bids,
               const int*   __restrict__ fids,
               float*       __restrict__ out,
               int nnz)
{
    const int b = blockIdx.x;
    const int t = threadIdx.x & (EMBED - 1);   // embedding dim
    const int g = threadIdx.x >> 6;            // group id 0..3

    // ---- segment bounds via binary search (all threads redundantly; broadcast loads) ----
    int lo = 0, cnt = nnz;
    while (cnt > 0) {
        int step = cnt >> 1;
        int m = lo + step;
        if (__ldg(bids + m) < b) { lo = m + 1; cnt -= step + 1; }
        else cnt = step;
    }
    int hi = lo; cnt = nnz - lo;
    while (cnt > 0) {
        int step = cnt >> 1;
        int m = hi + step;
        if (__ldg(bids + m) < b + 1) { hi = m + 1; cnt -= step + 1; }
        else cnt = step;
    }

    // ---- accumulate this group's slice of the segment ----
    float s = 0.f, q = 0.f;

    int i = lo + g;
    // unroll by 2 strides to get 2 outstanding gathers per thread
    for (; i + GROUPS < hi; i += 2 * GROUPS) {
        float v0 = __ldg(vals + i);
        int   f0 = __ldg(fids + i);
        float v1 = __ldg(vals + i + GROUPS);
        int   f1 = __ldg(fids + i + GROUPS);
        float e0 = __ldg(emb + (long long)f0 * EMBED + t);
        float e1 = __ldg(emb + (long long)f1 * EMBED + t);
        float ve0 = v0 * e0;
        float ve1 = v1 * e1;
        s += ve0; q += ve0 * ve0;
        s += ve1; q += ve1 * ve1;
    }
    if (i < hi) {
        float v = __ldg(vals + i);
        int   f = __ldg(fids + i);
        float e = __ldg(emb + (long long)f * EMBED + t);
        float ve = v * e;
        s += ve; q += ve * ve;
    }

    // ---- combine the 4 groups through shared memory ----
    __shared__ float ss[GROUPS][EMBED];
    __shared__ float sq[GROUPS][EMBED];
    ss[g][t] = s;
    sq[g][t] = q;
    __syncthreads();

    if (g == 0) {
        float S = s, Q = q;
        #pragma unroll
        for (int k = 1; k < GROUPS; k++) { S += ss[k][t]; Q += sq[k][t]; }
        out[b * EMBED + t] = 0.5f * (S * S - Q);
    }
}

extern "C" void kernel_launch(void* const* d_in, const int* in_sizes, int n_in,
                              void* d_out, int out_size)
{
    const float* emb  = (const float*)d_in[0];
    const float* vals = (const float*)d_in[1];
    const int*   bids = (const int*)d_in[2];
    const int*   fids = (const int*)d_in[3];
    float* out = (float*)d_out;

    int nnz   = in_sizes[1];
    int batch = out_size / EMBED;   // 4096

    fm_kernel<<<batch, BLOCK>>>(emb, vals, bids, fids, out, nnz);
}

// round 2
// speedup vs baseline: 1.9969x; 1.9969x over previous
#include <cuda_runtime.h>
#include <cuda_bf16.h>

// FM layer: out[b,:] = 0.5 * ((sum v*e)^2 - sum (v*e)^2), batch_ids sorted.
//
// Inputs:
//   d_in[0] feature_embedding float32 [1e6, 64]
//   d_in[1] feature_vals      float32 [819200]
//   d_in[2] batch_ids         int32   [819200] sorted
//   d_in[3] feat_ids          int32   [819200]
//   d_in[4] batch_size        int32   [1]
// Output float32 [4096, 64]

#define EMBED 64
#define GROUPS 8              // 8 independent 32-thread groups per CTA
#define BLOCK  256

__device__ int g_starts[4097];   // g_starts[b] = first i with bids[i] >= b

// Turn sorted batch_ids into CSR-style row starts. Thread i in [0, nnz]
// fills starts for every batch id strictly between bids[i-1] and bids[i]
// (inclusive of bids[i]); exactly-once, no atomics.
__global__ void boundary_kernel(const int* __restrict__ bids, int nnz, int batch)
{
    int i = blockIdx.x * blockDim.x + threadIdx.x;
    if (i > nnz) return;
    int prev = (i == 0)   ? -1    : __ldg(bids + i - 1);
    int cur  = (i == nnz) ? batch : __ldg(bids + i);
    for (int b = prev + 1; b <= cur; b++)
        g_starts[b] = i;
}

__global__ __launch_bounds__(BLOCK, 8)
void fm_main(const float* __restrict__ emb,
             const float* __restrict__ vals,
             const int*   __restrict__ fids,
             float*       __restrict__ out)
{
    const int b = blockIdx.x;
    const int t = threadIdx.x & 31;     // float2 lane: dims [2t, 2t+1]
    const int g = threadIdx.x >> 5;     // group 0..7

    const int lo = g_starts[b];
    const int hi = g_starts[b + 1];

    const float2* __restrict__ emb2 = (const float2*)emb;

    float sx = 0.f, sy = 0.f, qx = 0.f, qy = 0.f;

    int i = lo + g;
    // 4-deep gather pipeline per thread
    for (; i + 3 * GROUPS < hi; i += 4 * GROUPS) {
        int f0 = __ldg(fids + i);
        int f1 = __ldg(fids + i +     GROUPS);
        int f2 = __ldg(fids + i + 2 * GROUPS);
        int f3 = __ldg(fids + i + 3 * GROUPS);
        float v0 = __ldg(vals + i);
        float v1 = __ldg(vals + i +     GROUPS);
        float v2 = __ldg(vals + i + 2 * GROUPS);
        float v3 = __ldg(vals + i + 3 * GROUPS);
        float2 e0 = __ldg(emb2 + f0 * 32 + t);
        float2 e1 = __ldg(emb2 + f1 * 32 + t);
        float2 e2 = __ldg(emb2 + f2 * 32 + t);
        float2 e3 = __ldg(emb2 + f3 * 32 + t);

        float ax, ay;
        ax = v0 * e0.x; ay = v0 * e0.y; sx += ax; qx += ax * ax; sy += ay; qy += ay * ay;
        ax = v1 * e1.x; ay = v1 * e1.y; sx += ax; qx += ax * ax; sy += ay; qy += ay * ay;
        ax = v2 * e2.x; ay = v2 * e2.y; sx += ax; qx += ax * ax; sy += ay; qy += ay * ay;
        ax = v3 * e3.x; ay = v3 * e3.y; sx += ax; qx += ax * ax; sy += ay; qy += ay * ay;
    }
    for (; i < hi; i += GROUPS) {
        int   f = __ldg(fids + i);
        float v = __ldg(vals + i);
        float2 e = __ldg(emb2 + f * 32 + t);
        float ax = v * e.x, ay = v * e.y;
        sx += ax; qx += ax * ax; sy += ay; qy += ay * ay;
    }

    __shared__ float ssx[GROUPS][32], ssy[GROUPS][32];
    __shared__ float sqx[GROUPS][32], sqy[GROUPS][32];
    ssx[g][t] = sx; ssy[g][t] = sy;
    sqx[g][t] = qx; sqy[g][t] = qy;
    __syncthreads();

    if (g == 0) {
        float Sx = sx, Sy = sy, Qx = qx, Qy = qy;
        #pragma unroll
        for (int k = 1; k < GROUPS; k++) {
            Sx += ssx[k][t]; Sy += ssy[k][t];
            Qx += sqx[k][t]; Qy += sqy[k][t];
        }
        float2 o;
        o.x = 0.5f * (Sx * Sx - Qx);
        o.y = 0.5f * (Sy * Sy - Qy);
        ((float2*)out)[b * 32 + t] = o;
    }
}

extern "C" void kernel_launch(void* const* d_in, const int* in_sizes, int n_in,
                              void* d_out, int out_size)
{
    const float* emb  = (const float*)d_in[0];
    const float* vals = (const float*)d_in[1];
    const int*   bids = (const int*)d_in[2];
    const int*   fids = (const int*)d_in[3];
    float* out = (float*)d_out;

    int nnz   = in_sizes[1];
    int batch = out_size / EMBED;   // 4096

    int bblocks = (nnz + 1 + 255) / 256;
    boundary_kernel<<<bblocks, 256>>>(bids, nnz, batch);
    fm_main<<<batch, BLOCK>>>(emb, vals, fids, out);
}